// round 11
// baseline (speedup 1.0000x reference)
#include <cuda_runtime.h>
#include <cuda_bf16.h>
#include <cstdint>

#define T_LEN 4096
#define DEMB  256
#define HDIM  256
#define NGATE 1024          // 4*HDIM
#define TAGS  32
#define STARTT 30
#define STOPT  31
#define NEGV  (-10000.0f)

#define CSIZE 16            // CTAs per direction-cluster (non-portable size)

// ---------------- scratch (static device globals; no allocation) ----------------
__device__ __align__(16) float g_x[(size_t)T_LEN * DEMB];               // 4 MB
__device__ __align__(16) float g_xg[(size_t)2 * T_LEN * NGATE];         // 32 MB
__device__ __align__(16) float g_hs[(size_t)2 * T_LEN * HDIM];          // 8 MB
__device__ __align__(16) float g_feats[(size_t)T_LEN * TAGS];           // 512 KB

// ---------------- small helpers ----------------
__device__ __forceinline__ float sigf(float x)   { return 1.0f / (1.0f + __expf(-x)); }
__device__ __forceinline__ float tanh_f(float x) { return 1.0f - 2.0f / (__expf(2.0f * x) + 1.0f); }

__device__ __forceinline__ unsigned cluster_rank() {
    unsigned r; asm("mov.u32 %0, %%cluster_ctarank;" : "=r"(r)); return r;
}
__device__ __forceinline__ void cluster_sync_() {
    asm volatile("barrier.cluster.arrive.aligned;\n\tbarrier.cluster.wait.aligned;" ::: "memory");
}
__device__ __forceinline__ uint32_t smem_u32(const void* p) {
    return (uint32_t)__cvta_generic_to_shared(const_cast<void*>(p));
}
__device__ __forceinline__ uint32_t mapa_u32(uint32_t saddr, int r) {
    uint32_t d;
    asm("mapa.shared::cluster.u32 %0, %1, %2;" : "=r"(d) : "r"(saddr), "r"(r));
    return d;
}

// canonical mbarrier ops (forms from ptx_helpers.cuh; proven in R10)
#define MBAR_INIT(addr, cnt) \
    asm volatile("mbarrier.init.shared.b64 [%0], %1;" :: "r"(addr), "r"(cnt) : "memory")
#define MBAR_ARRIVE_REMOTE(remote_addr) \
    asm volatile("mbarrier.arrive.shared::cluster.b64 _, [%0];" :: "r"(remote_addr) : "memory")
#define MBAR_WAIT_PARITY(mbar, parity) do {                                             \
    uint32_t _m = (mbar); uint32_t _p = (parity); uint32_t _done;                       \
    asm volatile("{\n\t.reg .pred p;\n\t"                                               \
                 "mbarrier.try_wait.parity.acquire.cta.shared::cta.b64 p, [%1], %2;\n\t"\
                 "selp.b32 %0, 1, 0, p;\n\t}"                                           \
                 : "=r"(_done) : "r"(_m), "r"(_p) : "memory");                          \
    if (!_done) {                                                                       \
        asm volatile("{\n\t.reg .pred P1;\n\t"                                          \
            "W_%=:\n\t"                                                                 \
            "mbarrier.try_wait.parity.acquire.cta.shared::cta.b64 P1, [%0], %1, 0x989680;\n\t" \
            "@P1 bra.uni D_%=;\n\t"                                                     \
            "bra.uni W_%=;\n\t"                                                         \
            "D_%=:\n\t}" :: "r"(_m), "r"(_p) : "memory");                               \
    }                                                                                    \
} while (0)

// packed fp32x2 fma: acc = a*b + acc (full fp32, 2 MACs / instruction)
#define FMA2(acc, a, b) \
    asm("fma.rn.f32x2 %0, %1, %2, %3;" : "=l"(acc) : "l"(a), "l"(b), "l"(acc))

// ---------------- phase 1a: embedding gather ----------------
__global__ __launch_bounds__(256) void k_embed(const int* __restrict__ seq,
                                               const float* __restrict__ E) {
    int t = blockIdx.x;
    int d = threadIdx.x;
    g_x[(size_t)t * DEMB + d] = E[(size_t)seq[t] * DEMB + d];
}

// ---------------- phase 1b: input projections xg = x @ Wih^T + (bih+bhh) ----------------
__global__ __launch_bounds__(256) void k_xg(const float* __restrict__ WihF,
                                            const float* __restrict__ WihB,
                                            const float* __restrict__ bihF,
                                            const float* __restrict__ bhhF,
                                            const float* __restrict__ bihB,
                                            const float* __restrict__ bhhB) {
    const int BM = 64, BN = 64, BK = 16, PAD = 4;
    __shared__ __align__(16) float sA[BK][BM + PAD];
    __shared__ __align__(16) float sB[BK][BN + PAD];

    const int dir = blockIdx.z;
    const float* __restrict__ W  = dir ? WihB : WihF;
    const float* __restrict__ b1 = dir ? bihB : bihF;
    const float* __restrict__ b2 = dir ? bhhB : bhhF;

    const int n0 = blockIdx.x * BN;
    const int t0 = blockIdx.y * BM;
    const int tid = threadIdx.x;
    const int tx = tid & 15, ty = tid >> 4;
    const int lm = tid >> 2, lq = tid & 3;

    float acc[4][4];
#pragma unroll
    for (int i = 0; i < 4; i++)
#pragma unroll
        for (int j = 0; j < 4; j++) acc[i][j] = 0.0f;

    for (int k0 = 0; k0 < DEMB; k0 += BK) {
        float4 av = *reinterpret_cast<const float4*>(&g_x[(size_t)(t0 + lm) * DEMB + k0 + lq * 4]);
        float4 bv = *reinterpret_cast<const float4*>(&W[(size_t)(n0 + lm) * DEMB + k0 + lq * 4]);
        sA[lq * 4 + 0][lm] = av.x; sA[lq * 4 + 1][lm] = av.y;
        sA[lq * 4 + 2][lm] = av.z; sA[lq * 4 + 3][lm] = av.w;
        sB[lq * 4 + 0][lm] = bv.x; sB[lq * 4 + 1][lm] = bv.y;
        sB[lq * 4 + 2][lm] = bv.z; sB[lq * 4 + 3][lm] = bv.w;
        __syncthreads();
#pragma unroll
        for (int kk = 0; kk < BK; kk++) {
            float4 a4 = *reinterpret_cast<const float4*>(&sA[kk][ty * 4]);
            float4 b4 = *reinterpret_cast<const float4*>(&sB[kk][tx * 4]);
            float a[4] = {a4.x, a4.y, a4.z, a4.w};
            float b[4] = {b4.x, b4.y, b4.z, b4.w};
#pragma unroll
            for (int i = 0; i < 4; i++)
#pragma unroll
                for (int j = 0; j < 4; j++) acc[i][j] += a[i] * b[j];
        }
        __syncthreads();
    }
#pragma unroll
    for (int i = 0; i < 4; i++) {
        int row = t0 + ty * 4 + i;
#pragma unroll
        for (int j = 0; j < 4; j++) {
            int col = n0 + tx * 4 + j;
            g_xg[((size_t)dir * T_LEN + row) * NGATE + col] = acc[i][j] + b1[col] + b2[col];
        }
    }
}

// ---------------- phase 2: recurrence v8 --------------------------------------------------
// R10 protocol (proven) widened to CSIZE=16 CTAs per direction: CTA owns 16 hidden units,
// thread = (unit_local = tid>>4, chunk = tid&15); each thread covers 16 interleaved h cols
// {chunk*4 + j*64 + e} for all 4 gates (32 FMA2/thread -> CTA issue floor halved to ~128cy).
// Butterfly over 4 chunk bits; all 16 lanes of a group hold identical gate sums and run the
// activation redundantly; lane chunk==r pushes h to CTA r (one DSMEM store per lane).
// Sync: per-CTA double-buffered mbarriers, count=16 (one arrive per source CTA by tid<16
// after __syncthreads), fence.release before arrive / fence.acquire after wait.
// Launched WITHOUT __cluster_dims__; cluster dim 16 set at launch (non-portable size).
__global__ __launch_bounds__(256, 1)
void k_rec(const float* __restrict__ WhhF, const float* __restrict__ WhhB,
           const float* __restrict__ h0,   const float* __restrict__ c0) {
    __shared__ __align__(16) float h_sh[2][HDIM];
    __shared__ __align__(8) unsigned long long mbar[2];

    const int rank = (int)cluster_rank();
    const int dir  = (int)(blockIdx.x / CSIZE);
    const int tid  = threadIdx.x;
    const int unit_local = tid >> 4;              // 0..15
    const int chunk      = tid & 15;              // 0..15
    const int unit       = rank * 16 + unit_local;

    const float* __restrict__ Whh = dir ? WhhB : WhhF;

    // ---- register-resident weights: 4 gates x 4 interleaved float4s (as f32x2 pairs) ----
    unsigned long long w[4][8];
#pragma unroll
    for (int g = 0; g < 4; g++) {
        const float* wrow = Whh + ((size_t)g * HDIM + unit) * HDIM;
#pragma unroll
        for (int j = 0; j < 4; j++) {
            ulonglong2 v = *reinterpret_cast<const ulonglong2*>(wrow + j * 64 + chunk * 4);
            w[g][2 * j]     = v.x;
            w[g][2 * j + 1] = v.y;
        }
    }

    if (tid == 0) {
        MBAR_INIT(smem_u32(&mbar[0]), (uint32_t)CSIZE);
        MBAR_INIT(smem_u32(&mbar[1]), (uint32_t)CSIZE);
    }
    h_sh[0][tid] = h0[dir * HDIM + tid];
    h_sh[1][tid] = 0.0f;
    float c = c0[dir * HDIM + unit];              // replicated across the 16 lanes of a group
    __syncthreads();
    cluster_sync_();   // all CTAs' mbars + h_sh init done before any remote traffic

    // each lane pushes its group's h to CTA == its chunk; tid<16 own arrive to rank tid
    const uint32_t h_rem = mapa_u32(smem_u32(&h_sh[0][0]), chunk);
    uint32_t arr_rem = 0;
    if (tid < CSIZE) arr_rem = mapa_u32(smem_u32(&mbar[0]), tid);
    const uint32_t mb_loc = smem_u32(&mbar[0]);

    // xg pointer + initial prefetch (all lanes of a group load same addrs -> broadcast)
    const float* __restrict__ xgp = g_xg + (size_t)dir * T_LEN * NGATE + unit;
    float xgc[4];
    {
        const int t0 = dir ? (T_LEN - 1) : 0;
#pragma unroll
        for (int g = 0; g < 4; g++) xgc[g] = __ldg(xgp + (size_t)t0 * NGATE + g * HDIM);
    }

    float* __restrict__ hs_out = g_hs + (size_t)dir * T_LEN * HDIM + unit;

    for (int s = 0; s < T_LEN; s++) {
        const int t = dir ? (T_LEN - 1 - s) : s;
        const int b = s & 1;

        if (s) {
            MBAR_WAIT_PARITY(mb_loc + (uint32_t)b * 8u, (uint32_t)(((s - 1) >> 1) & 1));
            asm volatile("fence.acquire.cluster;" ::: "memory");   // see peers' h stores
        }

        // ---- dot: 4 gate rows over interleaved 16-elem subset, h loads reused 4x ----
        const float* hb = &h_sh[b][chunk * 4];
        unsigned long long acc[4] = {0ull, 0ull, 0ull, 0ull};
#pragma unroll
        for (int j = 0; j < 4; j++) {
            ulonglong2 hv = *reinterpret_cast<const ulonglong2*>(hb + j * 64);
#pragma unroll
            for (int g = 0; g < 4; g++) {
                FMA2(acc[g], w[g][2 * j],     hv.x);
                FMA2(acc[g], w[g][2 * j + 1], hv.y);
            }
        }

        float gs[4];
#pragma unroll
        for (int g = 0; g < 4; g++) {
            float lo, hi;
            asm("mov.b64 {%0,%1}, %2;" : "=f"(lo), "=f"(hi) : "l"(acc[g]));
            gs[g] = lo + hi;
        }
        // butterfly over chunk bits: all 16 lanes of a group get bit-identical sums
#pragma unroll
        for (int m = 1; m < 16; m <<= 1) {
#pragma unroll
            for (int g = 0; g < 4; g++)
                gs[g] += __shfl_xor_sync(0xffffffffu, gs[g], m);
        }

        // ---- activation: redundant in all 16 lanes (identical arithmetic) ----
        float gi = gs[0] + xgc[0];
        float gf = gs[1] + xgc[1];
        float gg = gs[2] + xgc[2];
        float go = gs[3] + xgc[3];
        float ii = sigf(gi), ff = sigf(gf), tg = tanh_f(gg), oo = sigf(go);
        c = ff * c + ii * tg;
        float h = oo * tanh_f(c);

        if (s + 1 < T_LEN) {
            // ONE instruction: each lane stores h into buf b^1 of CTA 'chunk'
            const uint32_t off = (uint32_t)(((b ^ 1) * HDIM + unit) * 4);
            asm volatile("st.shared::cluster.f32 [%0], %1;"
                         :: "r"(h_rem + off), "f"(h) : "memory");
        }
        __syncthreads();   // all 256 data stores ordered before the arrives below
        if (s + 1 < T_LEN && tid < CSIZE) {
            asm volatile("fence.release.cluster;" ::: "memory");   // publish data stores
            MBAR_ARRIVE_REMOTE(arr_rem + (uint32_t)(b ^ 1) * 8u);
        }

        // off the critical path: persist h, prefetch next xg
        if (chunk == 0) hs_out[(size_t)t * HDIM] = h;
        if (s + 1 < T_LEN) {
            const int tn = dir ? (T_LEN - 2 - s) : (s + 1);
#pragma unroll
            for (int g = 0; g < 4; g++) xgc[g] = __ldg(xgp + (size_t)tn * NGATE + g * HDIM);
        }
    }
    cluster_sync_();       // drain: no CTA exits while peer traffic could be in flight
    if (tid == 0) {
        asm volatile("mbarrier.inval.shared.b64 [%0];" :: "r"(mb_loc) : "memory");
        asm volatile("mbarrier.inval.shared.b64 [%0];" :: "r"(mb_loc + 8u) : "memory");
    }
}

// ---------------- phase 3: feats[t,k] = [hf(t);hb(t)] . W_out[k] + b_out[k] ----------------
__global__ __launch_bounds__(256) void k_feats(const float* __restrict__ Wout,
                                               const float* __restrict__ bout) {
    const int k  = threadIdx.x & 31;
    const int tl = threadIdx.x >> 5;
    const int t  = blockIdx.x * 8 + tl;
    const float4* hf = reinterpret_cast<const float4*>(g_hs + (size_t)t * HDIM);
    const float4* hb = reinterpret_cast<const float4*>(g_hs + (size_t)T_LEN * HDIM + (size_t)t * HDIM);
    const float4* wr = reinterpret_cast<const float4*>(Wout + (size_t)k * 512);
    float acc = bout[k];
#pragma unroll 8
    for (int d = 0; d < 64; d++) {
        float4 h4 = hf[d]; float4 w4 = wr[d];
        acc += h4.x * w4.x + h4.y * w4.y + h4.z * w4.z + h4.w * w4.w;
    }
#pragma unroll 8
    for (int d = 0; d < 64; d++) {
        float4 h4 = hb[d]; float4 w4 = wr[64 + d];
        acc += h4.x * w4.x + h4.y * w4.y + h4.z * w4.z + h4.w * w4.w;
    }
    g_feats[(size_t)t * TAGS + k] = acc;
}

// ---------------- phase 4: Viterbi v2 — tree-max (1 warp; bps in dyn smem) ----------------
__global__ void k_viterbi(const float* __restrict__ trans, float* __restrict__ out,
                          int out_size) {
    extern __shared__ unsigned char bps[];
    const int lane = threadIdx.x;

    float tr[TAGS];
#pragma unroll
    for (int p = 0; p < TAGS; p++) tr[p] = trans[lane * TAGS + p];
    const float trs = trans[STOPT * TAGS + lane];

    float fv = (lane == STARTT) ? 0.0f : NEGV;
    float fnext = g_feats[lane];
    for (int t = 0; t < T_LEN; t++) {
        const float feat = fnext;
        if (t + 1 < T_LEN) fnext = g_feats[(size_t)(t + 1) * TAGS + lane];

        float sc[TAGS];
#pragma unroll
        for (int p = 0; p < TAGS; p++)
            sc[p] = __shfl_sync(0xffffffffu, fv, p) + tr[p];

        float mv[16]; int mi[16];
#pragma unroll
        for (int i = 0; i < 16; i++) {
            bool take = sc[i + 16] > sc[i];
            mv[i] = take ? sc[i + 16] : sc[i];
            mi[i] = take ? (i + 16) : i;
        }
#pragma unroll
        for (int half = 8; half >= 1; half >>= 1) {
#pragma unroll
            for (int i = 0; i < half; i++) {
                bool take = mv[i + half] > mv[i];
                mv[i] = take ? mv[i + half] : mv[i];
                mi[i] = take ? mi[i + half] : mi[i];
            }
        }
        fv = mv[0] + feat;
        bps[(size_t)t * TAGS + lane] = (unsigned char)mi[0];
    }
    __syncwarp();

    float bv = fv + trs; int bidx = lane;
#pragma unroll
    for (int off = 16; off; off >>= 1) {
        float ov = __shfl_down_sync(0xffffffffu, bv, off);
        int   oi = __shfl_down_sync(0xffffffffu, bidx, off);
        if (ov > bv || (ov == bv && oi < bidx)) { bv = ov; bidx = oi; }
    }
    if (lane == 0) {
        const int off = (out_size > T_LEN) ? 1 : 0;
        if (off) out[0] = bv;
        int b = bidx;
        out[off + T_LEN - 1] = (float)b;
        for (int t = T_LEN - 1; t >= 1; --t) {
            b = (int)bps[(size_t)t * TAGS + b];
            out[off + t - 1] = (float)b;
        }
    }
}

// ---------------- launch ----------------
extern "C" void kernel_launch(void* const* d_in, const int* in_sizes, int n_in,
                              void* d_out, int out_size) {
    (void)in_sizes; (void)n_in;
    const int*   seq   = (const int*)  d_in[0];
    const float* E     = (const float*)d_in[1];
    const float* WihF  = (const float*)d_in[2];
    const float* WhhF  = (const float*)d_in[3];
    const float* bihF  = (const float*)d_in[4];
    const float* bhhF  = (const float*)d_in[5];
    const float* WihB  = (const float*)d_in[6];
    const float* WhhB  = (const float*)d_in[7];
    const float* bihB  = (const float*)d_in[8];
    const float* bhhB  = (const float*)d_in[9];
    const float* h0    = (const float*)d_in[10];
    const float* c0    = (const float*)d_in[11];
    const float* Wout  = (const float*)d_in[12];
    const float* bout  = (const float*)d_in[13];
    const float* trans = (const float*)d_in[14];
    float* out = (float*)d_out;

    k_embed<<<T_LEN, 256>>>(seq, E);
    dim3 gg(NGATE / 64, T_LEN / 64, 2);
    k_xg<<<gg, 256>>>(WihF, WihB, bihF, bhhF, bihB, bhhB);

    // k_rec: 2 clusters x 16 CTAs (non-portable cluster size, set at launch)
    static int rec_attr_done = 0;
    if (!rec_attr_done) {
        cudaFuncSetAttribute(k_rec, cudaFuncAttributeNonPortableClusterSizeAllowed, 1);
        rec_attr_done = 1;
    }
    {
        cudaLaunchConfig_t cfg = {};
        cfg.gridDim  = dim3(2 * CSIZE, 1, 1);
        cfg.blockDim = dim3(256, 1, 1);
        cfg.dynamicSmemBytes = 0;
        cfg.stream = 0;
        cudaLaunchAttribute attrs[1];
        attrs[0].id = cudaLaunchAttributeClusterDimension;
        attrs[0].val.clusterDim.x = CSIZE;
        attrs[0].val.clusterDim.y = 1;
        attrs[0].val.clusterDim.z = 1;
        cfg.attrs = attrs;
        cfg.numAttrs = 1;
        cudaLaunchKernelEx(&cfg, k_rec, WhhF, WhhB, h0, c0);
    }

    k_feats<<<T_LEN / 8, 256>>>(Wout, bout);
    cudaFuncSetAttribute(k_viterbi, cudaFuncAttributeMaxDynamicSharedMemorySize,
                         T_LEN * TAGS);
    k_viterbi<<<1, 32, T_LEN * TAGS>>>(trans, out, out_size);
}

// round 12
// speedup vs baseline: 1.0692x; 1.0692x over previous
#include <cuda_runtime.h>
#include <cuda_bf16.h>
#include <cstdint>

#define T_LEN 4096
#define DEMB  256
#define HDIM  256
#define NGATE 1024          // 4*HDIM
#define TAGS  32
#define STARTT 30
#define STOPT  31
#define NEGV  (-10000.0f)

// ---------------- scratch (static device globals; no allocation) ----------------
__device__ __align__(16) float g_x[(size_t)T_LEN * DEMB];               // 4 MB
__device__ __align__(16) float g_xg[(size_t)2 * T_LEN * NGATE];         // 32 MB
__device__ __align__(16) float g_hs[(size_t)2 * T_LEN * HDIM];          // 8 MB
__device__ __align__(16) float g_feats[(size_t)T_LEN * TAGS];           // 512 KB

// ---------------- small helpers ----------------
__device__ __forceinline__ float sigf(float x)   { return 1.0f / (1.0f + __expf(-x)); }
__device__ __forceinline__ float tanh_f(float x) { return 1.0f - 2.0f / (__expf(2.0f * x) + 1.0f); }

__device__ __forceinline__ unsigned cluster_rank() {
    unsigned r; asm("mov.u32 %0, %%cluster_ctarank;" : "=r"(r)); return r;
}
__device__ __forceinline__ void cluster_sync_() {
    asm volatile("barrier.cluster.arrive.aligned;\n\tbarrier.cluster.wait.aligned;" ::: "memory");
}
__device__ __forceinline__ uint32_t smem_u32(const void* p) {
    return (uint32_t)__cvta_generic_to_shared(const_cast<void*>(p));
}
__device__ __forceinline__ uint32_t mapa_u32(uint32_t saddr, int r) {
    uint32_t d;
    asm("mapa.shared::cluster.u32 %0, %1, %2;" : "=r"(d) : "r"(saddr), "r"(r));
    return d;
}

// canonical mbarrier ops (forms from ptx_helpers.cuh; proven in R10)
#define MBAR_INIT(addr, cnt) \
    asm volatile("mbarrier.init.shared.b64 [%0], %1;" :: "r"(addr), "r"(cnt) : "memory")
#define MBAR_ARRIVE_REMOTE(remote_addr) \
    asm volatile("mbarrier.arrive.shared::cluster.b64 _, [%0];" :: "r"(remote_addr) : "memory")
#define MBAR_WAIT_PARITY(mbar, parity) do {                                             \
    uint32_t _m = (mbar); uint32_t _p = (parity); uint32_t _done;                       \
    asm volatile("{\n\t.reg .pred p;\n\t"                                               \
                 "mbarrier.try_wait.parity.acquire.cta.shared::cta.b64 p, [%1], %2;\n\t"\
                 "selp.b32 %0, 1, 0, p;\n\t}"                                           \
                 : "=r"(_done) : "r"(_m), "r"(_p) : "memory");                          \
    if (!_done) {                                                                       \
        asm volatile("{\n\t.reg .pred P1;\n\t"                                          \
            "W_%=:\n\t"                                                                 \
            "mbarrier.try_wait.parity.acquire.cta.shared::cta.b64 P1, [%0], %1, 0x989680;\n\t" \
            "@P1 bra.uni D_%=;\n\t"                                                     \
            "bra.uni W_%=;\n\t"                                                         \
            "D_%=:\n\t}" :: "r"(_m), "r"(_p) : "memory");                               \
    }                                                                                    \
} while (0)

// packed fp32x2 fma: acc = a*b + acc (full fp32, 2 MACs / instruction)
#define FMA2(acc, a, b) \
    asm("fma.rn.f32x2 %0, %1, %2, %3;" : "=l"(acc) : "l"(a), "l"(b), "l"(acc))

// ---------------- no-op (shifts k_rec to ncu capture index 5) ----------------
__global__ void k_nop() {}

// ---------------- phase 1a: embedding gather ----------------
__global__ __launch_bounds__(256) void k_embed(const int* __restrict__ seq,
                                               const float* __restrict__ E) {
    int t = blockIdx.x;
    int d = threadIdx.x;
    g_x[(size_t)t * DEMB + d] = E[(size_t)seq[t] * DEMB + d];
}

// ---------------- phase 1b: input projections xg = x @ Wih^T + (bih+bhh) ----------------
__global__ __launch_bounds__(256) void k_xg(const float* __restrict__ WihF,
                                            const float* __restrict__ WihB,
                                            const float* __restrict__ bihF,
                                            const float* __restrict__ bhhF,
                                            const float* __restrict__ bihB,
                                            const float* __restrict__ bhhB) {
    const int BM = 64, BN = 64, BK = 16, PAD = 4;
    __shared__ __align__(16) float sA[BK][BM + PAD];
    __shared__ __align__(16) float sB[BK][BN + PAD];

    const int dir = blockIdx.z;
    const float* __restrict__ W  = dir ? WihB : WihF;
    const float* __restrict__ b1 = dir ? bihB : bihF;
    const float* __restrict__ b2 = dir ? bhhB : bhhF;

    const int n0 = blockIdx.x * BN;
    const int t0 = blockIdx.y * BM;
    const int tid = threadIdx.x;
    const int tx = tid & 15, ty = tid >> 4;
    const int lm = tid >> 2, lq = tid & 3;

    float acc[4][4];
#pragma unroll
    for (int i = 0; i < 4; i++)
#pragma unroll
        for (int j = 0; j < 4; j++) acc[i][j] = 0.0f;

    for (int k0 = 0; k0 < DEMB; k0 += BK) {
        float4 av = *reinterpret_cast<const float4*>(&g_x[(size_t)(t0 + lm) * DEMB + k0 + lq * 4]);
        float4 bv = *reinterpret_cast<const float4*>(&W[(size_t)(n0 + lm) * DEMB + k0 + lq * 4]);
        sA[lq * 4 + 0][lm] = av.x; sA[lq * 4 + 1][lm] = av.y;
        sA[lq * 4 + 2][lm] = av.z; sA[lq * 4 + 3][lm] = av.w;
        sB[lq * 4 + 0][lm] = bv.x; sB[lq * 4 + 1][lm] = bv.y;
        sB[lq * 4 + 2][lm] = bv.z; sB[lq * 4 + 3][lm] = bv.w;
        __syncthreads();
#pragma unroll
        for (int kk = 0; kk < BK; kk++) {
            float4 a4 = *reinterpret_cast<const float4*>(&sA[kk][ty * 4]);
            float4 b4 = *reinterpret_cast<const float4*>(&sB[kk][tx * 4]);
            float a[4] = {a4.x, a4.y, a4.z, a4.w};
            float b[4] = {b4.x, b4.y, b4.z, b4.w};
#pragma unroll
            for (int i = 0; i < 4; i++)
#pragma unroll
                for (int j = 0; j < 4; j++) acc[i][j] += a[i] * b[j];
        }
        __syncthreads();
    }
#pragma unroll
    for (int i = 0; i < 4; i++) {
        int row = t0 + ty * 4 + i;
#pragma unroll
        for (int j = 0; j < 4; j++) {
            int col = n0 + tx * 4 + j;
            g_xg[((size_t)dir * T_LEN + row) * NGATE + col] = acc[i][j] + b1[col] + b2[col];
        }
    }
}

// ---------------- phase 2: recurrence (R10 form — best known) -----------------------------
__global__ __launch_bounds__(256, 1) __cluster_dims__(8, 1, 1)
void k_rec(const float* __restrict__ WhhF, const float* __restrict__ WhhB,
           const float* __restrict__ h0,   const float* __restrict__ c0) {
    __shared__ __align__(16) float h_sh[2][HDIM];
    __shared__ __align__(8) unsigned long long mbar[2];

    const int rank = (int)cluster_rank();
    const int dir  = (int)(blockIdx.x >> 3);
    const int tid  = threadIdx.x;
    const int unit_local = tid >> 3;              // 0..31
    const int chunk      = tid & 7;               // 0..7
    const int unit       = rank * 32 + unit_local;

    const float* __restrict__ Whh = dir ? WhhB : WhhF;

    unsigned long long w[4][16];
#pragma unroll
    for (int g = 0; g < 4; g++) {
        const float* wrow = Whh + ((size_t)g * HDIM + unit) * HDIM;
#pragma unroll
        for (int j = 0; j < 8; j++) {
            ulonglong2 v = *reinterpret_cast<const ulonglong2*>(wrow + j * 32 + chunk * 4);
            w[g][2 * j]     = v.x;
            w[g][2 * j + 1] = v.y;
        }
    }

    if (tid == 0) {
        MBAR_INIT(smem_u32(&mbar[0]), 8u);
        MBAR_INIT(smem_u32(&mbar[1]), 8u);
    }
    h_sh[0][tid] = h0[dir * HDIM + tid];
    h_sh[1][tid] = 0.0f;
    float c = c0[dir * HDIM + unit];
    __syncthreads();
    cluster_sync_();

    const uint32_t h_rem = mapa_u32(smem_u32(&h_sh[0][0]), chunk);
    uint32_t arr_rem = 0;
    if (tid < 8) arr_rem = mapa_u32(smem_u32(&mbar[0]), tid);
    const uint32_t mb_loc = smem_u32(&mbar[0]);

    const float* __restrict__ xgp = g_xg + (size_t)dir * T_LEN * NGATE + unit;
    float xgc[4];
    {
        const int t0 = dir ? (T_LEN - 1) : 0;
#pragma unroll
        for (int g = 0; g < 4; g++) xgc[g] = __ldg(xgp + (size_t)t0 * NGATE + g * HDIM);
    }

    float* __restrict__ hs_out = g_hs + (size_t)dir * T_LEN * HDIM + unit;

    for (int s = 0; s < T_LEN; s++) {
        const int t = dir ? (T_LEN - 1 - s) : s;
        const int b = s & 1;

        if (s) {
            MBAR_WAIT_PARITY(mb_loc + (uint32_t)b * 8u, (uint32_t)(((s - 1) >> 1) & 1));
            asm volatile("fence.acquire.cluster;" ::: "memory");
        }

        const float* hb = &h_sh[b][chunk * 4];
        unsigned long long acc[4] = {0ull, 0ull, 0ull, 0ull};
#pragma unroll
        for (int j = 0; j < 8; j++) {
            ulonglong2 hv = *reinterpret_cast<const ulonglong2*>(hb + j * 32);
#pragma unroll
            for (int g = 0; g < 4; g++) {
                FMA2(acc[g], w[g][2 * j],     hv.x);
                FMA2(acc[g], w[g][2 * j + 1], hv.y);
            }
        }

        float gs[4];
#pragma unroll
        for (int g = 0; g < 4; g++) {
            float lo, hi;
            asm("mov.b64 {%0,%1}, %2;" : "=f"(lo), "=f"(hi) : "l"(acc[g]));
            gs[g] = lo + hi;
        }
#pragma unroll
        for (int m = 1; m < 8; m <<= 1) {
#pragma unroll
            for (int g = 0; g < 4; g++)
                gs[g] += __shfl_xor_sync(0xffffffffu, gs[g], m);
        }

        float gi = gs[0] + xgc[0];
        float gf = gs[1] + xgc[1];
        float gg = gs[2] + xgc[2];
        float go = gs[3] + xgc[3];
        float ii = sigf(gi), ff = sigf(gf), tg = tanh_f(gg), oo = sigf(go);
        c = ff * c + ii * tg;
        float h = oo * tanh_f(c);

        if (s + 1 < T_LEN) {
            const uint32_t off = (uint32_t)(((b ^ 1) * HDIM + unit) * 4);
            asm volatile("st.shared::cluster.f32 [%0], %1;"
                         :: "r"(h_rem + off), "f"(h) : "memory");
        }
        __syncthreads();
        if (s + 1 < T_LEN && tid < 8) {
            asm volatile("fence.release.cluster;" ::: "memory");
            MBAR_ARRIVE_REMOTE(arr_rem + (uint32_t)(b ^ 1) * 8u);
        }

        if (chunk == 0) hs_out[(size_t)t * HDIM] = h;
        if (s + 1 < T_LEN) {
            const int tn = dir ? (T_LEN - 2 - s) : (s + 1);
#pragma unroll
            for (int g = 0; g < 4; g++) xgc[g] = __ldg(xgp + (size_t)tn * NGATE + g * HDIM);
        }
    }
    cluster_sync_();
    if (tid == 0) {
        asm volatile("mbarrier.inval.shared.b64 [%0];" :: "r"(mb_loc) : "memory");
        asm volatile("mbarrier.inval.shared.b64 [%0];" :: "r"(mb_loc + 8u) : "memory");
    }
}

// ---------------- phase 3: feats[t,k] = [hf(t);hb(t)] . W_out[k] + b_out[k] ----------------
__global__ __launch_bounds__(256) void k_feats(const float* __restrict__ Wout,
                                               const float* __restrict__ bout) {
    const int k  = threadIdx.x & 31;
    const int tl = threadIdx.x >> 5;
    const int t  = blockIdx.x * 8 + tl;
    const float4* hf = reinterpret_cast<const float4*>(g_hs + (size_t)t * HDIM);
    const float4* hb = reinterpret_cast<const float4*>(g_hs + (size_t)T_LEN * HDIM + (size_t)t * HDIM);
    const float4* wr = reinterpret_cast<const float4*>(Wout + (size_t)k * 512);
    float acc = bout[k];
#pragma unroll 8
    for (int d = 0; d < 64; d++) {
        float4 h4 = hf[d]; float4 w4 = wr[d];
        acc += h4.x * w4.x + h4.y * w4.y + h4.z * w4.z + h4.w * w4.w;
    }
#pragma unroll 8
    for (int d = 0; d < 64; d++) {
        float4 h4 = hb[d]; float4 w4 = wr[64 + d];
        acc += h4.x * w4.x + h4.y * w4.y + h4.z * w4.z + h4.w * w4.w;
    }
    g_feats[(size_t)t * TAGS + k] = acc;
}

// ---------------- phase 4: Viterbi v3 — 128 threads, 4 per tag ----------------------------
// thread = tag*4 + sub; sub covers prevs [sub*8, sub*8+8) ascending. In-thread 3-level tree
// + 2 shfl_down levels, all "take right iff strictly greater" with left = lower prev index
// => identical first-max semantics to jnp.argmax. fv double-buffered in smem; ONE
// __syncthreads per step. Candidates are the same fv[p]+tr[n][p] FADDs as the reference.
__global__ __launch_bounds__(128) void k_viterbi(const float* __restrict__ trans,
                                                 float* __restrict__ out, int out_size) {
    extern __shared__ unsigned char bps[];          // T_LEN * TAGS bytes
    __shared__ __align__(16) float fvbuf[2][TAGS];

    const int tid = threadIdx.x;
    const int tag = tid >> 2;       // 0..31
    const int sub = tid & 3;        // 0..3
    const int base = sub * 8;

    float tr[8];
#pragma unroll
    for (int j = 0; j < 8; j++) tr[j] = trans[tag * TAGS + base + j];

    if (tid < TAGS) fvbuf[0][tid] = (tid == STARTT) ? 0.0f : NEGV;
    __syncthreads();

    float fnext = (sub == 0) ? __ldg(&g_feats[tag]) : 0.0f;

    for (int t = 0; t < T_LEN; t++) {
        const int b = t & 1;
        float4 f0 = *reinterpret_cast<const float4*>(&fvbuf[b][base]);
        float4 f1 = *reinterpret_cast<const float4*>(&fvbuf[b][base + 4]);
        float cand[8] = {f0.x + tr[0], f0.y + tr[1], f0.z + tr[2], f0.w + tr[3],
                         f1.x + tr[4], f1.y + tr[5], f1.z + tr[6], f1.w + tr[7]};
        float v[4]; int ix[4];
#pragma unroll
        for (int i = 0; i < 4; i++) {
            bool tk = cand[i + 4] > cand[i];
            v[i] = tk ? cand[i + 4] : cand[i];
            ix[i] = tk ? (i + 4) : i;
        }
#pragma unroll
        for (int i = 0; i < 2; i++) {
            bool tk = v[i + 2] > v[i];
            v[i] = tk ? v[i + 2] : v[i];
            ix[i] = tk ? ix[i + 2] : ix[i];
        }
        bool tk0 = v[1] > v[0];
        float bv = tk0 ? v[1] : v[0];
        int   bi = (tk0 ? ix[1] : ix[0]) + base;

        // cross-sub combine (lanes of one tag are contiguous; right = higher prevs)
        float ov = __shfl_down_sync(0xffffffffu, bv, 1);
        int   oi = __shfl_down_sync(0xffffffffu, bi, 1);
        if (ov > bv) { bv = ov; bi = oi; }         // valid at sub 0 (0|1) and sub 2 (2|3)
        ov = __shfl_down_sync(0xffffffffu, bv, 2);
        oi = __shfl_down_sync(0xffffffffu, bi, 2);
        if (ov > bv) { bv = ov; bi = oi; }         // valid at sub 0 (0..3)

        if (sub == 0) {
            const float feat = fnext;
            if (t + 1 < T_LEN) fnext = __ldg(&g_feats[(size_t)(t + 1) * TAGS + tag]);
            fvbuf[b ^ 1][tag] = bv + feat;
            bps[(size_t)t * TAGS + tag] = (unsigned char)bi;
        }
        __syncthreads();
    }

    if (tid < 32) {
        const int lane = tid;
        float bv = fvbuf[T_LEN & 1][lane] + trans[STOPT * TAGS + lane];
        int bidx = lane;
#pragma unroll
        for (int off = 16; off; off >>= 1) {
            float ov = __shfl_down_sync(0xffffffffu, bv, off);
            int   oi = __shfl_down_sync(0xffffffffu, bidx, off);
            if (ov > bv || (ov == bv && oi < bidx)) { bv = ov; bidx = oi; }
        }
        if (lane == 0) {
            const int off = (out_size > T_LEN) ? 1 : 0;
            if (off) out[0] = bv;
            int b = bidx;
            out[off + T_LEN - 1] = (float)b;
            for (int t = T_LEN - 1; t >= 1; --t) {
                b = (int)bps[(size_t)t * TAGS + b];
                out[off + t - 1] = (float)b;
            }
        }
    }
}

// ---------------- launch ----------------
extern "C" void kernel_launch(void* const* d_in, const int* in_sizes, int n_in,
                              void* d_out, int out_size) {
    (void)in_sizes; (void)n_in;
    const int*   seq   = (const int*)  d_in[0];
    const float* E     = (const float*)d_in[1];
    const float* WihF  = (const float*)d_in[2];
    const float* WhhF  = (const float*)d_in[3];
    const float* bihF  = (const float*)d_in[4];
    const float* bhhF  = (const float*)d_in[5];
    const float* WihB  = (const float*)d_in[6];
    const float* WhhB  = (const float*)d_in[7];
    const float* bihB  = (const float*)d_in[8];
    const float* bhhB  = (const float*)d_in[9];
    const float* h0    = (const float*)d_in[10];
    const float* c0    = (const float*)d_in[11];
    const float* Wout  = (const float*)d_in[12];
    const float* bout  = (const float*)d_in[13];
    const float* trans = (const float*)d_in[14];
    float* out = (float*)d_out;

    k_embed<<<T_LEN, 256>>>(seq, E);
    dim3 gg(NGATE / 64, T_LEN / 64, 2);
    k_xg<<<gg, 256>>>(WihF, WihB, bihF, bhhF, bihB, bhhB);
    // shift k_rec to global launch index 5 so ncu (-s 5 -c 1) captures it
    k_nop<<<1, 1>>>();
    k_nop<<<1, 1>>>();
    k_nop<<<1, 1>>>();
    k_rec<<<16, 256>>>(WhhF, WhhB, h0, c0);
    k_feats<<<T_LEN / 8, 256>>>(Wout, bout);
    cudaFuncSetAttribute(k_viterbi, cudaFuncAttributeMaxDynamicSharedMemorySize,
                         T_LEN * TAGS);
    k_viterbi<<<1, 128, T_LEN * TAGS>>>(trans, out, out_size);
}

// round 13
// speedup vs baseline: 1.1174x; 1.0451x over previous
#include <cuda_runtime.h>
#include <cuda_bf16.h>
#include <cstdint>

#define T_LEN 4096
#define DEMB  256
#define HDIM  256
#define NGATE 1024          // 4*HDIM
#define TAGS  32
#define STARTT 30
#define STOPT  31
#define NEGV  (-10000.0f)

// ---------------- scratch (static device globals; no allocation) ----------------
__device__ __align__(16) float g_x[(size_t)T_LEN * DEMB];               // 4 MB
__device__ __align__(16) float g_xg[(size_t)2 * T_LEN * NGATE];         // 32 MB
__device__ __align__(16) float g_hs[(size_t)2 * T_LEN * HDIM];          // 8 MB
__device__ __align__(16) float g_feats[(size_t)T_LEN * TAGS];           // 512 KB

// ---------------- small helpers ----------------
__device__ __forceinline__ float sigf(float x)   { return 1.0f / (1.0f + __expf(-x)); }
__device__ __forceinline__ float tanh_f(float x) { return 1.0f - 2.0f / (__expf(2.0f * x) + 1.0f); }

__device__ __forceinline__ unsigned cluster_rank() {
    unsigned r; asm("mov.u32 %0, %%cluster_ctarank;" : "=r"(r)); return r;
}
__device__ __forceinline__ void cluster_sync_() {
    asm volatile("barrier.cluster.arrive.aligned;\n\tbarrier.cluster.wait.aligned;" ::: "memory");
}
__device__ __forceinline__ uint32_t smem_u32(const void* p) {
    return (uint32_t)__cvta_generic_to_shared(const_cast<void*>(p));
}
__device__ __forceinline__ uint32_t mapa_u32(uint32_t saddr, int r) {
    uint32_t d;
    asm("mapa.shared::cluster.u32 %0, %1, %2;" : "=r"(d) : "r"(saddr), "r"(r));
    return d;
}

// canonical mbarrier ops (forms from ptx_helpers.cuh; proven in R10)
#define MBAR_INIT(addr, cnt) \
    asm volatile("mbarrier.init.shared.b64 [%0], %1;" :: "r"(addr), "r"(cnt) : "memory")
#define MBAR_ARRIVE_REMOTE(remote_addr) \
    asm volatile("mbarrier.arrive.shared::cluster.b64 _, [%0];" :: "r"(remote_addr) : "memory")
#define MBAR_WAIT_PARITY(mbar, parity) do {                                             \
    uint32_t _m = (mbar); uint32_t _p = (parity); uint32_t _done;                       \
    asm volatile("{\n\t.reg .pred p;\n\t"                                               \
                 "mbarrier.try_wait.parity.acquire.cta.shared::cta.b64 p, [%1], %2;\n\t"\
                 "selp.b32 %0, 1, 0, p;\n\t}"                                           \
                 : "=r"(_done) : "r"(_m), "r"(_p) : "memory");                          \
    if (!_done) {                                                                       \
        asm volatile("{\n\t.reg .pred P1;\n\t"                                          \
            "W_%=:\n\t"                                                                 \
            "mbarrier.try_wait.parity.acquire.cta.shared::cta.b64 P1, [%0], %1, 0x989680;\n\t" \
            "@P1 bra.uni D_%=;\n\t"                                                     \
            "bra.uni W_%=;\n\t"                                                         \
            "D_%=:\n\t}" :: "r"(_m), "r"(_p) : "memory");                               \
    }                                                                                    \
} while (0)

// packed fp32x2 fma: acc = a*b + acc (full fp32, 2 MACs / instruction)
#define FMA2(acc, a, b) \
    asm("fma.rn.f32x2 %0, %1, %2, %3;" : "=l"(acc) : "l"(a), "l"(b), "l"(acc))

// ---------------- no-op (aligns k_rec to ncu capture index 5: 2 harness + embed + xg + nop)
__global__ void k_nop() {}

// ---------------- phase 1a: embedding gather ----------------
__global__ __launch_bounds__(256) void k_embed(const int* __restrict__ seq,
                                               const float* __restrict__ E) {
    int t = blockIdx.x;
    int d = threadIdx.x;
    g_x[(size_t)t * DEMB + d] = E[(size_t)seq[t] * DEMB + d];
}

// ---------------- phase 1b: input projections xg = x @ Wih^T + (bih+bhh) ----------------
__global__ __launch_bounds__(256) void k_xg(const float* __restrict__ WihF,
                                            const float* __restrict__ WihB,
                                            const float* __restrict__ bihF,
                                            const float* __restrict__ bhhF,
                                            const float* __restrict__ bihB,
                                            const float* __restrict__ bhhB) {
    const int BM = 64, BN = 64, BK = 16, PAD = 4;
    __shared__ __align__(16) float sA[BK][BM + PAD];
    __shared__ __align__(16) float sB[BK][BN + PAD];

    const int dir = blockIdx.z;
    const float* __restrict__ W  = dir ? WihB : WihF;
    const float* __restrict__ b1 = dir ? bihB : bihF;
    const float* __restrict__ b2 = dir ? bhhB : bhhF;

    const int n0 = blockIdx.x * BN;
    const int t0 = blockIdx.y * BM;
    const int tid = threadIdx.x;
    const int tx = tid & 15, ty = tid >> 4;
    const int lm = tid >> 2, lq = tid & 3;

    float acc[4][4];
#pragma unroll
    for (int i = 0; i < 4; i++)
#pragma unroll
        for (int j = 0; j < 4; j++) acc[i][j] = 0.0f;

    for (int k0 = 0; k0 < DEMB; k0 += BK) {
        float4 av = *reinterpret_cast<const float4*>(&g_x[(size_t)(t0 + lm) * DEMB + k0 + lq * 4]);
        float4 bv = *reinterpret_cast<const float4*>(&W[(size_t)(n0 + lm) * DEMB + k0 + lq * 4]);
        sA[lq * 4 + 0][lm] = av.x; sA[lq * 4 + 1][lm] = av.y;
        sA[lq * 4 + 2][lm] = av.z; sA[lq * 4 + 3][lm] = av.w;
        sB[lq * 4 + 0][lm] = bv.x; sB[lq * 4 + 1][lm] = bv.y;
        sB[lq * 4 + 2][lm] = bv.z; sB[lq * 4 + 3][lm] = bv.w;
        __syncthreads();
#pragma unroll
        for (int kk = 0; kk < BK; kk++) {
            float4 a4 = *reinterpret_cast<const float4*>(&sA[kk][ty * 4]);
            float4 b4 = *reinterpret_cast<const float4*>(&sB[kk][tx * 4]);
            float a[4] = {a4.x, a4.y, a4.z, a4.w};
            float b[4] = {b4.x, b4.y, b4.z, b4.w};
#pragma unroll
            for (int i = 0; i < 4; i++)
#pragma unroll
                for (int j = 0; j < 4; j++) acc[i][j] += a[i] * b[j];
        }
        __syncthreads();
    }
#pragma unroll
    for (int i = 0; i < 4; i++) {
        int row = t0 + ty * 4 + i;
#pragma unroll
        for (int j = 0; j < 4; j++) {
            int col = n0 + tx * 4 + j;
            g_xg[((size_t)dir * T_LEN + row) * NGATE + col] = acc[i][j] + b1[col] + b2[col];
        }
    }
}

// ---------------- phase 2: recurrence (R10 form — best known, unmodified) -----------------
__global__ __launch_bounds__(256, 1) __cluster_dims__(8, 1, 1)
void k_rec(const float* __restrict__ WhhF, const float* __restrict__ WhhB,
           const float* __restrict__ h0,   const float* __restrict__ c0) {
    __shared__ __align__(16) float h_sh[2][HDIM];
    __shared__ __align__(8) unsigned long long mbar[2];

    const int rank = (int)cluster_rank();
    const int dir  = (int)(blockIdx.x >> 3);
    const int tid  = threadIdx.x;
    const int unit_local = tid >> 3;              // 0..31
    const int chunk      = tid & 7;               // 0..7
    const int unit       = rank * 32 + unit_local;

    const float* __restrict__ Whh = dir ? WhhB : WhhF;

    unsigned long long w[4][16];
#pragma unroll
    for (int g = 0; g < 4; g++) {
        const float* wrow = Whh + ((size_t)g * HDIM + unit) * HDIM;
#pragma unroll
        for (int j = 0; j < 8; j++) {
            ulonglong2 v = *reinterpret_cast<const ulonglong2*>(wrow + j * 32 + chunk * 4);
            w[g][2 * j]     = v.x;
            w[g][2 * j + 1] = v.y;
        }
    }

    if (tid == 0) {
        MBAR_INIT(smem_u32(&mbar[0]), 8u);
        MBAR_INIT(smem_u32(&mbar[1]), 8u);
    }
    h_sh[0][tid] = h0[dir * HDIM + tid];
    h_sh[1][tid] = 0.0f;
    float c = c0[dir * HDIM + unit];
    __syncthreads();
    cluster_sync_();

    const uint32_t h_rem = mapa_u32(smem_u32(&h_sh[0][0]), chunk);
    uint32_t arr_rem = 0;
    if (tid < 8) arr_rem = mapa_u32(smem_u32(&mbar[0]), tid);
    const uint32_t mb_loc = smem_u32(&mbar[0]);

    const float* __restrict__ xgp = g_xg + (size_t)dir * T_LEN * NGATE + unit;
    float xgc[4];
    {
        const int t0 = dir ? (T_LEN - 1) : 0;
#pragma unroll
        for (int g = 0; g < 4; g++) xgc[g] = __ldg(xgp + (size_t)t0 * NGATE + g * HDIM);
    }

    float* __restrict__ hs_out = g_hs + (size_t)dir * T_LEN * HDIM + unit;

    for (int s = 0; s < T_LEN; s++) {
        const int t = dir ? (T_LEN - 1 - s) : s;
        const int b = s & 1;

        if (s) {
            MBAR_WAIT_PARITY(mb_loc + (uint32_t)b * 8u, (uint32_t)(((s - 1) >> 1) & 1));
            asm volatile("fence.acquire.cluster;" ::: "memory");
        }

        const float* hb = &h_sh[b][chunk * 4];
        unsigned long long acc[4] = {0ull, 0ull, 0ull, 0ull};
#pragma unroll
        for (int j = 0; j < 8; j++) {
            ulonglong2 hv = *reinterpret_cast<const ulonglong2*>(hb + j * 32);
#pragma unroll
            for (int g = 0; g < 4; g++) {
                FMA2(acc[g], w[g][2 * j],     hv.x);
                FMA2(acc[g], w[g][2 * j + 1], hv.y);
            }
        }

        float gs[4];
#pragma unroll
        for (int g = 0; g < 4; g++) {
            float lo, hi;
            asm("mov.b64 {%0,%1}, %2;" : "=f"(lo), "=f"(hi) : "l"(acc[g]));
            gs[g] = lo + hi;
        }
#pragma unroll
        for (int m = 1; m < 8; m <<= 1) {
#pragma unroll
            for (int g = 0; g < 4; g++)
                gs[g] += __shfl_xor_sync(0xffffffffu, gs[g], m);
        }

        float gi = gs[0] + xgc[0];
        float gf = gs[1] + xgc[1];
        float gg = gs[2] + xgc[2];
        float go = gs[3] + xgc[3];
        float ii = sigf(gi), ff = sigf(gf), tg = tanh_f(gg), oo = sigf(go);
        c = ff * c + ii * tg;
        float h = oo * tanh_f(c);

        if (s + 1 < T_LEN) {
            const uint32_t off = (uint32_t)(((b ^ 1) * HDIM + unit) * 4);
            asm volatile("st.shared::cluster.f32 [%0], %1;"
                         :: "r"(h_rem + off), "f"(h) : "memory");
        }
        __syncthreads();
        if (s + 1 < T_LEN && tid < 8) {
            asm volatile("fence.release.cluster;" ::: "memory");
            MBAR_ARRIVE_REMOTE(arr_rem + (uint32_t)(b ^ 1) * 8u);
        }

        if (chunk == 0) hs_out[(size_t)t * HDIM] = h;
        if (s + 1 < T_LEN) {
            const int tn = dir ? (T_LEN - 2 - s) : (s + 1);
#pragma unroll
            for (int g = 0; g < 4; g++) xgc[g] = __ldg(xgp + (size_t)tn * NGATE + g * HDIM);
        }
    }
    cluster_sync_();
    if (tid == 0) {
        asm volatile("mbarrier.inval.shared.b64 [%0];" :: "r"(mb_loc) : "memory");
        asm volatile("mbarrier.inval.shared.b64 [%0];" :: "r"(mb_loc + 8u) : "memory");
    }
}

// ---------------- phase 3: feats[t,k] = [hf(t);hb(t)] . W_out[k] + b_out[k] ----------------
__global__ __launch_bounds__(256) void k_feats(const float* __restrict__ Wout,
                                               const float* __restrict__ bout) {
    const int k  = threadIdx.x & 31;
    const int tl = threadIdx.x >> 5;
    const int t  = blockIdx.x * 8 + tl;
    const float4* hf = reinterpret_cast<const float4*>(g_hs + (size_t)t * HDIM);
    const float4* hb = reinterpret_cast<const float4*>(g_hs + (size_t)T_LEN * HDIM + (size_t)t * HDIM);
    const float4* wr = reinterpret_cast<const float4*>(Wout + (size_t)k * 512);
    float acc = bout[k];
#pragma unroll 8
    for (int d = 0; d < 64; d++) {
        float4 h4 = hf[d]; float4 w4 = wr[d];
        acc += h4.x * w4.x + h4.y * w4.y + h4.z * w4.z + h4.w * w4.w;
    }
#pragma unroll 8
    for (int d = 0; d < 64; d++) {
        float4 h4 = hb[d]; float4 w4 = wr[64 + d];
        acc += h4.x * w4.x + h4.y * w4.y + h4.z * w4.z + h4.w * w4.w;
    }
    g_feats[(size_t)t * TAGS + k] = acc;
}

// ---------------- phase 4: Viterbi v2 — tree-max (1 warp; bps in dyn smem) ----------------
// (restored from R9/R10 — the 128-thread v3 regressed: smem+BAR per step beat by pure shfl)
__global__ void k_viterbi(const float* __restrict__ trans, float* __restrict__ out,
                          int out_size) {
    extern __shared__ unsigned char bps[];
    const int lane = threadIdx.x;

    float tr[TAGS];
#pragma unroll
    for (int p = 0; p < TAGS; p++) tr[p] = trans[lane * TAGS + p];
    const float trs = trans[STOPT * TAGS + lane];

    float fv = (lane == STARTT) ? 0.0f : NEGV;
    float fnext = g_feats[lane];
    for (int t = 0; t < T_LEN; t++) {
        const float feat = fnext;
        if (t + 1 < T_LEN) fnext = g_feats[(size_t)(t + 1) * TAGS + lane];

        float sc[TAGS];
#pragma unroll
        for (int p = 0; p < TAGS; p++)
            sc[p] = __shfl_sync(0xffffffffu, fv, p) + tr[p];

        float mv[16]; int mi[16];
#pragma unroll
        for (int i = 0; i < 16; i++) {
            bool take = sc[i + 16] > sc[i];
            mv[i] = take ? sc[i + 16] : sc[i];
            mi[i] = take ? (i + 16) : i;
        }
#pragma unroll
        for (int half = 8; half >= 1; half >>= 1) {
#pragma unroll
            for (int i = 0; i < half; i++) {
                bool take = mv[i + half] > mv[i];
                mv[i] = take ? mv[i + half] : mv[i];
                mi[i] = take ? mi[i + half] : mi[i];
            }
        }
        fv = mv[0] + feat;
        bps[(size_t)t * TAGS + lane] = (unsigned char)mi[0];
    }
    __syncwarp();

    float bv = fv + trs; int bidx = lane;
#pragma unroll
    for (int off = 16; off; off >>= 1) {
        float ov = __shfl_down_sync(0xffffffffu, bv, off);
        int   oi = __shfl_down_sync(0xffffffffu, bidx, off);
        if (ov > bv || (ov == bv && oi < bidx)) { bv = ov; bidx = oi; }
    }
    if (lane == 0) {
        const int off = (out_size > T_LEN) ? 1 : 0;
        if (off) out[0] = bv;
        int b = bidx;
        out[off + T_LEN - 1] = (float)b;
        for (int t = T_LEN - 1; t >= 1; --t) {
            b = (int)bps[(size_t)t * TAGS + b];
            out[off + t - 1] = (float)b;
        }
    }
}

// ---------------- launch ----------------
extern "C" void kernel_launch(void* const* d_in, const int* in_sizes, int n_in,
                              void* d_out, int out_size) {
    (void)in_sizes; (void)n_in;
    const int*   seq   = (const int*)  d_in[0];
    const float* E     = (const float*)d_in[1];
    const float* WihF  = (const float*)d_in[2];
    const float* WhhF  = (const float*)d_in[3];
    const float* bihF  = (const float*)d_in[4];
    const float* bhhF  = (const float*)d_in[5];
    const float* WihB  = (const float*)d_in[6];
    const float* WhhB  = (const float*)d_in[7];
    const float* bihB  = (const float*)d_in[8];
    const float* bhhB  = (const float*)d_in[9];
    const float* h0    = (const float*)d_in[10];
    const float* c0    = (const float*)d_in[11];
    const float* Wout  = (const float*)d_in[12];
    const float* bout  = (const float*)d_in[13];
    const float* trans = (const float*)d_in[14];
    float* out = (float*)d_out;

    k_embed<<<T_LEN, 256>>>(seq, E);
    dim3 gg(NGATE / 64, T_LEN / 64, 2);
    k_xg<<<gg, 256>>>(WihF, WihB, bihF, bhhF, bihB, bhhB);
    // exactly ONE nop: 2 harness launches + embed + xg + nop -> k_rec at ncu index 5
    k_nop<<<1, 1>>>();
    k_rec<<<16, 256>>>(WhhF, WhhB, h0, c0);
    k_feats<<<T_LEN / 8, 256>>>(Wout, bout);
    cudaFuncSetAttribute(k_viterbi, cudaFuncAttributeMaxDynamicSharedMemorySize,
                         T_LEN * TAGS);
    k_viterbi<<<1, 32, T_LEN * TAGS>>>(trans, out, out_size);
}

// round 15
// speedup vs baseline: 1.4294x; 1.2792x over previous
#include <cuda_runtime.h>
#include <cuda_bf16.h>
#include <cstdint>

#define T_LEN 4096
#define DEMB  256
#define HDIM  256
#define NGATE 1024          // 4*HDIM
#define TAGS  32
#define STARTT 30
#define STOPT  31
#define NEGV  (-10000.0f)

// ---------------- scratch (static device globals; no allocation) ----------------
__device__ __align__(16) float g_x[(size_t)T_LEN * DEMB];               // 4 MB
__device__ __align__(16) float g_xg[(size_t)2 * T_LEN * NGATE];         // 32 MB
__device__ __align__(16) float g_hs[(size_t)2 * T_LEN * HDIM];          // 8 MB
__device__ __align__(16) float g_feats[(size_t)T_LEN * TAGS];           // 512 KB

// ---------------- small helpers ----------------
__device__ __forceinline__ float sigf(float x)   { return 1.0f / (1.0f + __expf(-x)); }
__device__ __forceinline__ float tanh_f(float x) { return 1.0f - 2.0f / (__expf(2.0f * x) + 1.0f); }

__device__ __forceinline__ unsigned cluster_rank() {
    unsigned r; asm("mov.u32 %0, %%cluster_ctarank;" : "=r"(r)); return r;
}
__device__ __forceinline__ void cluster_sync_() {
    asm volatile("barrier.cluster.arrive.aligned;\n\tbarrier.cluster.wait.aligned;" ::: "memory");
}
__device__ __forceinline__ uint32_t smem_u32(const void* p) {
    return (uint32_t)__cvta_generic_to_shared(const_cast<void*>(p));
}
__device__ __forceinline__ uint32_t mapa_u32(uint32_t saddr, int r) {
    uint32_t d;
    asm("mapa.shared::cluster.u32 %0, %1, %2;" : "=r"(d) : "r"(saddr), "r"(r));
    return d;
}

// canonical mbarrier ops
#define MBAR_INIT(addr, cnt) \
    asm volatile("mbarrier.init.shared.b64 [%0], %1;" :: "r"(addr), "r"(cnt) : "memory")
#define MBAR_EXPECT_TX(addr, bytes) \
    asm volatile("mbarrier.arrive.expect_tx.shared.b64 _, [%0], %1;" \
                 :: "r"(addr), "r"(bytes) : "memory")
#define MBAR_WAIT_PARITY(mbar, parity) do {                                             \
    uint32_t _m = (mbar); uint32_t _p = (parity); uint32_t _done;                       \
    asm volatile("{\n\t.reg .pred p;\n\t"                                               \
                 "mbarrier.try_wait.parity.acquire.cta.shared::cta.b64 p, [%1], %2;\n\t"\
                 "selp.b32 %0, 1, 0, p;\n\t}"                                           \
                 : "=r"(_done) : "r"(_m), "r"(_p) : "memory");                          \
    if (!_done) {                                                                       \
        asm volatile("{\n\t.reg .pred P1;\n\t"                                          \
            "W_%=:\n\t"                                                                 \
            "mbarrier.try_wait.parity.acquire.cta.shared::cta.b64 P1, [%0], %1, 0x989680;\n\t" \
            "@P1 bra.uni D_%=;\n\t"                                                     \
            "bra.uni W_%=;\n\t"                                                         \
            "D_%=:\n\t}" :: "r"(_m), "r"(_p) : "memory");                               \
    }                                                                                    \
} while (0)

// self-signaling remote store: data + 4B tx delivered to the target CTA's mbarrier
#define ST_ASYNC_F32(remote_addr, val, remote_mbar) \
    asm volatile("st.async.shared::cluster.mbarrier::complete_tx::bytes.f32 [%0], %1, [%2];" \
                 :: "r"(remote_addr), "f"(val), "r"(remote_mbar) : "memory")

// packed fp32x2 fma: acc = a*b + acc (full fp32, 2 MACs / instruction)
#define FMA2(acc, a, b) \
    asm("fma.rn.f32x2 %0, %1, %2, %3;" : "=l"(acc) : "l"(a), "l"(b), "l"(acc))

// ---------------- no-op (aligns k_rec to ncu capture index 5) ----------------
__global__ void k_nop() {}

// ---------------- phase 1a: embedding gather ----------------
__global__ __launch_bounds__(256) void k_embed(const int* __restrict__ seq,
                                               const float* __restrict__ E) {
    int t = blockIdx.x;
    int d = threadIdx.x;
    g_x[(size_t)t * DEMB + d] = E[(size_t)seq[t] * DEMB + d];
}

// ---------------- phase 1b: input projections xg = x @ Wih^T + (bih+bhh) ----------------
__global__ __launch_bounds__(256) void k_xg(const float* __restrict__ WihF,
                                            const float* __restrict__ WihB,
                                            const float* __restrict__ bihF,
                                            const float* __restrict__ bhhF,
                                            const float* __restrict__ bihB,
                                            const float* __restrict__ bhhB) {
    const int BM = 64, BN = 64, BK = 16, PAD = 4;
    __shared__ __align__(16) float sA[BK][BM + PAD];
    __shared__ __align__(16) float sB[BK][BN + PAD];

    const int dir = blockIdx.z;
    const float* __restrict__ W  = dir ? WihB : WihF;
    const float* __restrict__ b1 = dir ? bihB : bihF;
    const float* __restrict__ b2 = dir ? bhhB : bhhF;

    const int n0 = blockIdx.x * BN;
    const int t0 = blockIdx.y * BM;
    const int tid = threadIdx.x;
    const int tx = tid & 15, ty = tid >> 4;
    const int lm = tid >> 2, lq = tid & 3;

    float acc[4][4];
#pragma unroll
    for (int i = 0; i < 4; i++)
#pragma unroll
        for (int j = 0; j < 4; j++) acc[i][j] = 0.0f;

    for (int k0 = 0; k0 < DEMB; k0 += BK) {
        float4 av = *reinterpret_cast<const float4*>(&g_x[(size_t)(t0 + lm) * DEMB + k0 + lq * 4]);
        float4 bv = *reinterpret_cast<const float4*>(&W[(size_t)(n0 + lm) * DEMB + k0 + lq * 4]);
        sA[lq * 4 + 0][lm] = av.x; sA[lq * 4 + 1][lm] = av.y;
        sA[lq * 4 + 2][lm] = av.z; sA[lq * 4 + 3][lm] = av.w;
        sB[lq * 4 + 0][lm] = bv.x; sB[lq * 4 + 1][lm] = bv.y;
        sB[lq * 4 + 2][lm] = bv.z; sB[lq * 4 + 3][lm] = bv.w;
        __syncthreads();
#pragma unroll
        for (int kk = 0; kk < BK; kk++) {
            float4 a4 = *reinterpret_cast<const float4*>(&sA[kk][ty * 4]);
            float4 b4 = *reinterpret_cast<const float4*>(&sB[kk][tx * 4]);
            float a[4] = {a4.x, a4.y, a4.z, a4.w};
            float b[4] = {b4.x, b4.y, b4.z, b4.w};
#pragma unroll
            for (int i = 0; i < 4; i++)
#pragma unroll
                for (int j = 0; j < 4; j++) acc[i][j] += a[i] * b[j];
        }
        __syncthreads();
    }
#pragma unroll
    for (int i = 0; i < 4; i++) {
        int row = t0 + ty * 4 + i;
#pragma unroll
        for (int j = 0; j < 4; j++) {
            int col = n0 + tx * 4 + j;
            g_xg[((size_t)dir * T_LEN + row) * NGATE + col] = acc[i][j] + b1[col] + b2[col];
        }
    }
}

// ---------------- phase 2: recurrence v9 — st.async self-signaling exchange ---------------
// R10 compute engine. Sync: every lane's remote h store is st.async with complete_tx to the
// target CTA's mbarrier (data+signal fused). Consumer: tid0 issues arrive.expect_tx(1024)
// per phase (8 src CTAs x 32 units x 4B) on its own mbar; all threads try_wait.
// No per-step __syncthreads / fences / separate arrives.
// Overwrite safety (double buffer): tx-complete of step-(s+1) data requires ALL lanes of
// ALL CTAs to have issued their store, each ordered after that lane's step-(s+1) dot-read
// (butterfly shfl syncs the warp's reads) => passing wait(s+2) implies every warp finished
// step-(s+1) (hence step-s) reads, so writes into buf[b] at s+2 cannot clobber readers.
__global__ __launch_bounds__(256, 1) __cluster_dims__(8, 1, 1)
void k_rec(const float* __restrict__ WhhF, const float* __restrict__ WhhB,
           const float* __restrict__ h0,   const float* __restrict__ c0) {
    __shared__ __align__(16) float h_sh[2][HDIM];
    __shared__ __align__(8) unsigned long long mbar[2];

    const int rank = (int)cluster_rank();
    const int dir  = (int)(blockIdx.x >> 3);
    const int tid  = threadIdx.x;
    const int unit_local = tid >> 3;              // 0..31
    const int chunk      = tid & 7;               // 0..7
    const int unit       = rank * 32 + unit_local;

    const float* __restrict__ Whh = dir ? WhhB : WhhF;

    unsigned long long w[4][16];
#pragma unroll
    for (int g = 0; g < 4; g++) {
        const float* wrow = Whh + ((size_t)g * HDIM + unit) * HDIM;
#pragma unroll
        for (int j = 0; j < 8; j++) {
            ulonglong2 v = *reinterpret_cast<const ulonglong2*>(wrow + j * 32 + chunk * 4);
            w[g][2 * j]     = v.x;
            w[g][2 * j + 1] = v.y;
        }
    }

    if (tid == 0) {
        MBAR_INIT(smem_u32(&mbar[0]), 1u);   // one arrive (the expect_tx) + 1024B tx / phase
        MBAR_INIT(smem_u32(&mbar[1]), 1u);
    }
    h_sh[0][tid] = h0[dir * HDIM + tid];
    h_sh[1][tid] = 0.0f;
    float c = c0[dir * HDIM + unit];
    __syncthreads();
    cluster_sync_();   // peers' mbars + h_sh init complete before any remote store

    // lane targets CTA == chunk: data addr base and that CTA's mbar base
    const uint32_t h_rem  = mapa_u32(smem_u32(&h_sh[0][0]), chunk);
    const uint32_t mb_rem = mapa_u32(smem_u32(&mbar[0]), chunk);
    const uint32_t mb_loc = smem_u32(&mbar[0]);

    const float* __restrict__ xgp = g_xg + (size_t)dir * T_LEN * NGATE + unit;
    float xgc[4];
    {
        const int t0 = dir ? (T_LEN - 1) : 0;
#pragma unroll
        for (int g = 0; g < 4; g++) xgc[g] = __ldg(xgp + (size_t)t0 * NGATE + g * HDIM);
    }

    float* __restrict__ hs_out = g_hs + (size_t)dir * T_LEN * HDIM + unit;

    for (int s = 0; s < T_LEN; s++) {
        const int t = dir ? (T_LEN - 1 - s) : s;
        const int b = s & 1;

        // prepare my mbar[b^1] for the stores carrying step-(s+1) data
        if (s + 1 < T_LEN && tid == 0)
            MBAR_EXPECT_TX(mb_loc + (uint32_t)(b ^ 1) * 8u, 1024u);

        if (s) MBAR_WAIT_PARITY(mb_loc + (uint32_t)b * 8u, (uint32_t)(((s - 1) >> 1) & 1));

        const float* hb = &h_sh[b][chunk * 4];
        unsigned long long acc[4] = {0ull, 0ull, 0ull, 0ull};
#pragma unroll
        for (int j = 0; j < 8; j++) {
            ulonglong2 hv = *reinterpret_cast<const ulonglong2*>(hb + j * 32);
#pragma unroll
            for (int g = 0; g < 4; g++) {
                FMA2(acc[g], w[g][2 * j],     hv.x);
                FMA2(acc[g], w[g][2 * j + 1], hv.y);
            }
        }

        float gs[4];
#pragma unroll
        for (int g = 0; g < 4; g++) {
            float lo, hi;
            asm("mov.b64 {%0,%1}, %2;" : "=f"(lo), "=f"(hi) : "l"(acc[g]));
            gs[g] = lo + hi;
        }
#pragma unroll
        for (int m = 1; m < 8; m <<= 1) {
#pragma unroll
            for (int g = 0; g < 4; g++)
                gs[g] += __shfl_xor_sync(0xffffffffu, gs[g], m);
        }

        float gi = gs[0] + xgc[0];
        float gf = gs[1] + xgc[1];
        float gg = gs[2] + xgc[2];
        float go = gs[3] + xgc[3];
        float ii = sigf(gi), ff = sigf(gf), tg = tanh_f(gg), oo = sigf(go);
        c = ff * c + ii * tg;
        float h = oo * tanh_f(c);

        if (s + 1 < T_LEN) {
            // self-signaling store: h -> buf b^1 of CTA 'chunk', tx -> that CTA's mbar[b^1]
            const uint32_t off = (uint32_t)(((b ^ 1) * HDIM + unit) * 4);
            ST_ASYNC_F32(h_rem + off, h, mb_rem + (uint32_t)(b ^ 1) * 8u);
        }

        // off the critical path: persist h, prefetch next xg
        if (chunk == 0) hs_out[(size_t)t * HDIM] = h;
        if (s + 1 < T_LEN) {
            const int tn = dir ? (T_LEN - 2 - s) : (s + 1);
#pragma unroll
            for (int g = 0; g < 4; g++) xgc[g] = __ldg(xgp + (size_t)tn * NGATE + g * HDIM);
        }
    }
    cluster_sync_();   // drain: no CTA exits while peer traffic could be in flight
    if (tid == 0) {
        asm volatile("mbarrier.inval.shared.b64 [%0];" :: "r"(mb_loc) : "memory");
        asm volatile("mbarrier.inval.shared.b64 [%0];" :: "r"(mb_loc + 8u) : "memory");
    }
}

// ---------------- phase 3: feats[t,k] = [hf(t);hb(t)] . W_out[k] + b_out[k] ----------------
__global__ __launch_bounds__(256) void k_feats(const float* __restrict__ Wout,
                                               const float* __restrict__ bout) {
    const int k  = threadIdx.x & 31;
    const int tl = threadIdx.x >> 5;
    const int t  = blockIdx.x * 8 + tl;
    const float4* hf = reinterpret_cast<const float4*>(g_hs + (size_t)t * HDIM);
    const float4* hb = reinterpret_cast<const float4*>(g_hs + (size_t)T_LEN * HDIM + (size_t)t * HDIM);
    const float4* wr = reinterpret_cast<const float4*>(Wout + (size_t)k * 512);
    float acc = bout[k];
#pragma unroll 8
    for (int d = 0; d < 64; d++) {
        float4 h4 = hf[d]; float4 w4 = wr[d];
        acc += h4.x * w4.x + h4.y * w4.y + h4.z * w4.z + h4.w * w4.w;
    }
#pragma unroll 8
    for (int d = 0; d < 64; d++) {
        float4 h4 = hb[d]; float4 w4 = wr[64 + d];
        acc += h4.x * w4.x + h4.y * w4.y + h4.z * w4.z + h4.w * w4.w;
    }
    g_feats[(size_t)t * TAGS + k] = acc;
}

// ---------------- phase 4: Viterbi v2 — tree-max (1 warp; bps in dyn smem) ----------------
__global__ void k_viterbi(const float* __restrict__ trans, float* __restrict__ out,
                          int out_size) {
    extern __shared__ unsigned char bps[];
    const int lane = threadIdx.x;

    float tr[TAGS];
#pragma unroll
    for (int p = 0; p < TAGS; p++) tr[p] = trans[lane * TAGS + p];
    const float trs = trans[STOPT * TAGS + lane];

    float fv = (lane == STARTT) ? 0.0f : NEGV;
    float fnext = g_feats[lane];
    for (int t = 0; t < T_LEN; t++) {
        const float feat = fnext;
        if (t + 1 < T_LEN) fnext = g_feats[(size_t)(t + 1) * TAGS + lane];

        float sc[TAGS];
#pragma unroll
        for (int p = 0; p < TAGS; p++)
            sc[p] = __shfl_sync(0xffffffffu, fv, p) + tr[p];

        float mv[16]; int mi[16];
#pragma unroll
        for (int i = 0; i < 16; i++) {
            bool take = sc[i + 16] > sc[i];
            mv[i] = take ? sc[i + 16] : sc[i];
            mi[i] = take ? (i + 16) : i;
        }
#pragma unroll
        for (int half = 8; half >= 1; half >>= 1) {
#pragma unroll
            for (int i = 0; i < half; i++) {
                bool take = mv[i + half] > mv[i];
                mv[i] = take ? mv[i + half] : mv[i];
                mi[i] = take ? mi[i + half] : mi[i];
            }
        }
        fv = mv[0] + feat;
        bps[(size_t)t * TAGS + lane] = (unsigned char)mi[0];
    }
    __syncwarp();

    float bv = fv + trs; int bidx = lane;
#pragma unroll
    for (int off = 16; off; off >>= 1) {
        float ov = __shfl_down_sync(0xffffffffu, bv, off);
        int   oi = __shfl_down_sync(0xffffffffu, bidx, off);
        if (ov > bv || (ov == bv && oi < bidx)) { bv = ov; bidx = oi; }
    }
    if (lane == 0) {
        const int off = (out_size > T_LEN) ? 1 : 0;
        if (off) out[0] = bv;
        int b = bidx;
        out[off + T_LEN - 1] = (float)b;
        for (int t = T_LEN - 1; t >= 1; --t) {
            b = (int)bps[(size_t)t * TAGS + b];
            out[off + t - 1] = (float)b;
        }
    }
}

// ---------------- launch ----------------
extern "C" void kernel_launch(void* const* d_in, const int* in_sizes, int n_in,
                              void* d_out, int out_size) {
    (void)in_sizes; (void)n_in;
    const int*   seq   = (const int*)  d_in[0];
    const float* E     = (const float*)d_in[1];
    const float* WihF  = (const float*)d_in[2];
    const float* WhhF  = (const float*)d_in[3];
    const float* bihF  = (const float*)d_in[4];
    const float* bhhF  = (const float*)d_in[5];
    const float* WihB  = (const float*)d_in[6];
    const float* WhhB  = (const float*)d_in[7];
    const float* bihB  = (const float*)d_in[8];
    const float* bhhB  = (const float*)d_in[9];
    const float* h0    = (const float*)d_in[10];
    const float* c0    = (const float*)d_in[11];
    const float* Wout  = (const float*)d_in[12];
    const float* bout  = (const float*)d_in[13];
    const float* trans = (const float*)d_in[14];
    float* out = (float*)d_out;

    k_embed<<<T_LEN, 256>>>(seq, E);
    dim3 gg(NGATE / 64, T_LEN / 64, 2);
    k_xg<<<gg, 256>>>(WihF, WihB, bihF, bhhF, bihB, bhhB);
    // ONE nop: 2 harness launches + embed + xg + nop -> k_rec at ncu index 5
    k_nop<<<1, 1>>>();
    k_rec<<<16, 256>>>(WhhF, WhhB, h0, c0);
    k_feats<<<T_LEN / 8, 256>>>(Wout, bout);
    cudaFuncSetAttribute(k_viterbi, cudaFuncAttributeMaxDynamicSharedMemorySize,
                         T_LEN * TAGS);
    k_viterbi<<<1, 32, T_LEN * TAGS>>>(trans, out, out_size);
}